// round 2
// baseline (speedup 1.0000x reference)
#include <cuda_runtime.h>

#define NBATCH 4
#define NQ 2048
#define NF 16384
#define CDIM 768
#define SCALEF 0.57735026918962576f  // 1/sqrt(3)

#define TQ 16    // query rows per CTA in attn kernel
#define CK 32    // key chunk size
#define TPB 192  // threads per CTA: each owns 4 output columns (192*4 = 768)

// Scratch: projected q/k, padded to float4 for vector loads (w unused).
__device__ __align__(16) float4 g_qp[NBATCH * NQ];
__device__ __align__(16) float4 g_kp[NBATCH * NF];

// ---- packed f32x2 helpers (FFMA2: 2x fp32 FMA throughput, PTX-only) ----
__device__ __forceinline__ unsigned long long pack2(float lo, float hi) {
    unsigned long long u;
    asm("mov.b64 %0, {%1, %2};" : "=l"(u) : "f"(lo), "f"(hi));
    return u;
}
__device__ __forceinline__ void fma2(unsigned long long& a, unsigned long long b,
                                     unsigned long long c) {
    asm("fma.rn.f32x2 %0, %1, %2, %0;" : "+l"(a) : "l"(b), "l"(c));
}
__device__ __forceinline__ void unpack2(unsigned long long a, float& lo, float& hi) {
    asm("mov.b64 {%0, %1}, %2;" : "=f"(lo), "=f"(hi) : "l"(a));
}

// ---- Kernel 1: tiny 3x3 projections + ReLU for q and k ----
__global__ void proj_kernel(const float* __restrict__ q, const float* __restrict__ k,
                            const float* __restrict__ W1, const float* __restrict__ b1,
                            const float* __restrict__ W2, const float* __restrict__ b2) {
    int i = blockIdx.x * blockDim.x + threadIdx.x;
    const int nq = NBATCH * NQ;
    const int nf = NBATCH * NF;
    if (i < nq) {
        float x0 = q[3 * i], x1 = q[3 * i + 1], x2 = q[3 * i + 2];
        float4 o;
        o.x = fmaxf(0.f, fmaf(W1[0], x0, fmaf(W1[1], x1, fmaf(W1[2], x2, b1[0]))));
        o.y = fmaxf(0.f, fmaf(W1[3], x0, fmaf(W1[4], x1, fmaf(W1[5], x2, b1[1]))));
        o.z = fmaxf(0.f, fmaf(W1[6], x0, fmaf(W1[7], x1, fmaf(W1[8], x2, b1[2]))));
        o.w = 0.f;
        g_qp[i] = o;
    } else if (i < nq + nf) {
        int j = i - nq;
        float x0 = k[3 * j], x1 = k[3 * j + 1], x2 = k[3 * j + 2];
        float4 o;
        o.x = fmaxf(0.f, fmaf(W2[0], x0, fmaf(W2[1], x1, fmaf(W2[2], x2, b2[0]))));
        o.y = fmaxf(0.f, fmaf(W2[3], x0, fmaf(W2[4], x1, fmaf(W2[5], x2, b2[1]))));
        o.z = fmaxf(0.f, fmaf(W2[6], x0, fmaf(W2[7], x1, fmaf(W2[8], x2, b2[2]))));
        o.w = 0.f;
        g_kp[j] = o;
    }
}

// ---- Kernel 2: fused softmax stats + (p @ v) accumulation ----
// Grid: (NQ/TQ, NBATCH). Each CTA: 16 query rows x all 768 columns.
// Thread t owns columns [4t, 4t+4). Accumulators: 8 row-pairs x 4 cols as f32x2.
__global__ void __launch_bounds__(TPB) attn_kernel(const float* __restrict__ v,
                                                   float* __restrict__ out) {
    const int b = blockIdx.y;
    const int r0 = blockIdx.x * TQ;
    const float4* __restrict__ kp = g_kp + b * NF;
    const float4* __restrict__ qpb = g_qp + b * NQ + r0;
    const float* __restrict__ vb = v + (size_t)b * NF * CDIM;

    __shared__ __align__(16) float4 qp_s[TQ];
    __shared__ float row_m[TQ];
    __shared__ float row_il[TQ];
    __shared__ float2 st[TPB];
    __shared__ __align__(16) float p_s[CK][TQ];  // p_s[key][row]

    const int tid = threadIdx.x;
    if (tid < TQ) qp_s[tid] = qpb[tid];
    __syncthreads();

    // ---- Phase A: per-row softmax stats (online max/sumexp), 12 threads/row ----
    {
        const int r = tid & 15;
        const int j = tid >> 4;  // 0..11
        float4 qv = qp_s[r];
        float mx = -1e30f, l = 0.f;
        for (int mm = j; mm < NF; mm += 12) {
            float4 kv = kp[mm];
            float s = (qv.x * kv.x + qv.y * kv.y + qv.z * kv.z) * SCALEF;
            float nm = fmaxf(mx, s);
            l = l * __expf(mx - nm) + __expf(s - nm);
            mx = nm;
        }
        st[tid] = make_float2(mx, l);
    }
    __syncthreads();
    if (tid < TQ) {
        float mx = -1e30f, l = 0.f;
        #pragma unroll
        for (int j = 0; j < 12; j++) {
            float2 e = st[(j << 4) + tid];
            float nm = fmaxf(mx, e.x);
            l = l * __expf(mx - nm) + e.y * __expf(e.x - nm);
            mx = nm;
        }
        row_m[tid] = mx;
        row_il[tid] = 1.f / l;
    }
    __syncthreads();

    // ---- Phase B: out[r][c] = sum_m p[r][m] * v[m][c] ----
    // acc[g][c]: f32x2 holding rows (2g, 2g+1) for column c0+c.
    unsigned long long acc[8][4];
    #pragma unroll
    for (int g = 0; g < 8; g++)
        #pragma unroll
        for (int c = 0; c < 4; c++) acc[g][c] = 0ull;

    const int c0 = tid << 2;
    const float* __restrict__ vcol = vb + c0;

    for (int m0 = 0; m0 < NF; m0 += CK) {
        // compute normalized p chunk into shared (512 values over 192 threads)
        for (int idx = tid; idx < CK * TQ; idx += TPB) {
            int mm = idx >> 4;
            int r = idx & 15;
            float4 kv = kp[m0 + mm];
            float4 qv = qp_s[r];
            float s = (qv.x * kv.x + qv.y * kv.y + qv.z * kv.z) * SCALEF;
            p_s[mm][r] = __expf(s - row_m[r]) * row_il[r];
        }
        __syncthreads();

        #pragma unroll 4
        for (int mm = 0; mm < CK; mm++) {
            float4 vv = *reinterpret_cast<const float4*>(vcol + (m0 + mm) * CDIM);
            unsigned long long vx = pack2(vv.x, vv.x);
            unsigned long long vy = pack2(vv.y, vv.y);
            unsigned long long vz = pack2(vv.z, vv.z);
            unsigned long long vw = pack2(vv.w, vv.w);
            // p row-pairs: LDS.128 gives 4 consecutive rows = 2 packed pairs
            const ulonglong2* pp = reinterpret_cast<const ulonglong2*>(&p_s[mm][0]);
            #pragma unroll
            for (int g = 0; g < 4; g++) {
                ulonglong2 p2 = pp[g];  // p2.x = rows(4g,4g+1), p2.y = rows(4g+2,4g+3)
                fma2(acc[2 * g][0], p2.x, vx);
                fma2(acc[2 * g][1], p2.x, vy);
                fma2(acc[2 * g][2], p2.x, vz);
                fma2(acc[2 * g][3], p2.x, vw);
                fma2(acc[2 * g + 1][0], p2.y, vx);
                fma2(acc[2 * g + 1][1], p2.y, vy);
                fma2(acc[2 * g + 1][2], p2.y, vz);
                fma2(acc[2 * g + 1][3], p2.y, vw);
            }
        }
        __syncthreads();
    }

    // ---- Epilogue: unpack row pairs, vectorized stores ----
    float* orow = out + ((size_t)b * NQ + r0) * CDIM + c0;
    #pragma unroll
    for (int g = 0; g < 8; g++) {
        float lo0, hi0, lo1, hi1, lo2, hi2, lo3, hi3;
        unpack2(acc[g][0], lo0, hi0);
        unpack2(acc[g][1], lo1, hi1);
        unpack2(acc[g][2], lo2, hi2);
        unpack2(acc[g][3], lo3, hi3);
        *reinterpret_cast<float4*>(orow + (2 * g) * CDIM) = make_float4(lo0, lo1, lo2, lo3);
        *reinterpret_cast<float4*>(orow + (2 * g + 1) * CDIM) = make_float4(hi0, hi1, hi2, hi3);
    }
}

extern "C" void kernel_launch(void* const* d_in, const int* in_sizes, int n_in,
                              void* d_out, int out_size) {
    const float* q  = (const float*)d_in[0];
    const float* k  = (const float*)d_in[1];
    const float* v  = (const float*)d_in[2];
    const float* W1 = (const float*)d_in[3];
    const float* b1 = (const float*)d_in[4];
    const float* W2 = (const float*)d_in[5];
    const float* b2 = (const float*)d_in[6];
    float* out = (float*)d_out;

    const int total = NBATCH * (NQ + NF);
    proj_kernel<<<(total + 255) / 256, 256>>>(q, k, W1, b1, W2, b2);

    dim3 grid(NQ / TQ, NBATCH);
    attn_kernel<<<grid, TPB>>>(v, out);
}